// round 7
// baseline (speedup 1.0000x reference)
#include <cuda_runtime.h>
#include <math.h>
#include <stdint.h>

#define BB   16
#define NN   256
#define DD   64
#define KTOP 128
#define NT   8          // 256/32 tiles per dim
#define NPAIR 36        // NT*(NT+1)/2

// Scratch (no device allocations allowed)
__device__ float g_logits[BB * NN * NN];   // 4 MB
__device__ float g_h[BB * NN * DD];
__device__ float g_scores[BB * NN];

// ---------------- packed f32x2 helpers ----------------
__device__ __forceinline__ unsigned long long pack2f(float a, float b) {
    unsigned long long r;
    asm("mov.b64 %0, {%1, %2};" : "=l"(r) : "f"(a), "f"(b));
    return r;
}
__device__ __forceinline__ void fma2(unsigned long long& d,
                                     unsigned long long a,
                                     unsigned long long b) {
    asm("fma.rn.f32x2 %0, %1, %2, %0;" : "+l"(d) : "l"(a), "l"(b));
}
__device__ __forceinline__ unsigned long long mul2(unsigned long long a,
                                                   unsigned long long b) {
    unsigned long long r;
    asm("mul.rn.f32x2 %0, %1, %2;" : "=l"(r) : "l"(a), "l"(b));
    return r;
}
__device__ __forceinline__ float2 unpack2f(unsigned long long v) {
    float lo, hi;
    asm("mov.b64 {%0, %1}, %2;" : "=f"(lo), "=f"(hi) : "l"(v));
    float2 r; r.x = lo; r.y = hi;
    return r;
}
__device__ __forceinline__ float ex2f(float x) {
    float y; asm("ex2.approx.f32 %0, %1;" : "=f"(y) : "f"(x)); return y;
}
__device__ __forceinline__ float rcpf(float x) {
    float y; asm("rcp.approx.f32 %0, %1;" : "=f"(y) : "f"(x)); return y;
}

#define C2LOG2E 2.8853900817779268f   // 2*log2(e)
#define LOG2E   1.4426950408889634f

// ---------------- k1a smem layout (bytes) ----------------
#define SM_XIP  0                      // [64][16] u64  i-pair values
#define SM_XJD  8192                   // [64][32] u64  j dup pairs
#define SM_WD   24576                  // [64][68] u64  W dup pairs (eh at +34)
#define SM_EP   59392                  // [8][32][2] f32 partials
#define SM_BW   61440                  // 64 float2
#define SM_BASE 61952                  // 2 f32 (+pad)
#define SM_TILE 61968                  // [32][33] f32 logit tile
#define SM_TOT1 (SM_TILE + 4224)

// =====================================================================
// Kernel 1a: symmetric logits. grid (36 tile-pairs, 16 b), block 256.
// =====================================================================
__global__ __launch_bounds__(256, 2)
void k1a_logits(const float* __restrict__ x,
                const float* __restrict__ Watt,
                const float* __restrict__ batt_g,
                const float* __restrict__ attw_g)
{
    extern __shared__ char sm[];
    unsigned long long* xip  = (unsigned long long*)(sm + SM_XIP);
    unsigned long long* xjd  = (unsigned long long*)(sm + SM_XJD);
    unsigned long long* wdup = (unsigned long long*)(sm + SM_WD);
    float*  ep   = (float*)(sm + SM_EP);
    float2* bw2  = (float2*)(sm + SM_BW);
    float*  base = (float*)(sm + SM_BASE);
    float*  tile = (float*)(sm + SM_TILE);

    const int tid = threadIdx.x;
    const int b   = blockIdx.y;

    // decode triangle tile pair
    int p = blockIdx.x, ti = 0;
    while (p >= NT - ti) { p -= NT - ti; ++ti; }
    const int tj = ti + p;
    const int i0 = ti * 32, j0 = tj * 32;

    const float* xb = x + (size_t)b * NN * DD;

    for (int t = tid; t < 1024; t += 256) {          // xip[d][ipg]
        int ipg = t >> 6, d = t & 63;
        float a = xb[(size_t)(i0 + 2 * ipg) * DD + d];
        float c = xb[(size_t)(i0 + 2 * ipg + 1) * DD + d];
        xip[d * 16 + ipg] = pack2f(a, c);
    }
    for (int t = tid; t < 2048; t += 256) {          // xjd[d][j] dup
        int j = t >> 6, d = t & 63;
        float v = xb[(size_t)(j0 + j) * DD + d];
        xjd[d * 32 + j] = pack2f(v, v);
    }
    for (int t = tid; t < 4096; t += 256) {          // wdup[d][slot] dup
        int d = t >> 6, e = t & 63;
        float w = __ldg(Watt + t);
        int slot = (e < 32) ? e : (e + 2);           // eh=1 at +34
        wdup[d * 68 + slot] = pack2f(w, w);
    }
    if (tid < 64) {
        float aww = attw_g[tid];
        bw2[tid] = make_float2(batt_g[tid] * C2LOG2E, -aww);
    }
    __syncthreads();
    if (tid < 2) {
        float s = 0.f;
        #pragma unroll
        for (int e = 0; e < 32; ++e) s -= bw2[tid * 32 + e].y;   // +aw
        base[tid] = 0.5f * s;
    }
    __syncthreads();

    const int ip = tid >> 6;            // 0..3
    const int jl = (tid >> 1) & 31;     // j lane
    const int eh = tid & 1;             // e half

    const unsigned long long* xip_p = xip + ip;
    const unsigned long long* xjd_p = xjd + jl;
    const char* wd_p = (const char*)(wdup + eh * 34);

    for (int pass = 0; pass < 4; ++pass) {
        unsigned long long acc[32];
        #pragma unroll
        for (int k = 0; k < 32; ++k) acc[k] = 0ull;

        const unsigned long long* xv = xip_p + pass * 4;

        #pragma unroll 4
        for (int d = 0; d < 64; ++d) {
            unsigned long long xp = xv[d * 16];
            unsigned long long xj = xjd_p[d * 32];
            unsigned long long pp = mul2(xp, xj);
            const ulonglong2* wr = (const ulonglong2*)(wd_p + d * 544);
            #pragma unroll
            for (int h = 0; h < 16; ++h) {
                ulonglong2 wv = wr[h];
                fma2(acc[2 * h + 0], pp, wv.x);
                fma2(acc[2 * h + 1], pp, wv.y);
            }
        }

        // epilogue: tanh + dot(aw) for the two i-lanes
        float pl0 = base[eh], pl1 = base[eh];
        #pragma unroll
        for (int k = 0; k < 32; ++k) {
            float2 bc = bw2[eh * 32 + k];
            float2 v = unpack2f(acc[k]);
            float r0 = rcpf(ex2f(fmaf(v.x, C2LOG2E, bc.x)) + 1.f);
            float r1 = rcpf(ex2f(fmaf(v.y, C2LOG2E, bc.x)) + 1.f);
            pl0 = fmaf(bc.y, r0, pl0);
            pl1 = fmaf(bc.y, r1, pl1);
        }
        ep[(2 * ip + 0) * 64 + jl * 2 + eh] = pl0;
        ep[(2 * ip + 1) * 64 + jl * 2 + eh] = pl1;
        __syncthreads();

        // combine eh halves; direct store + stage for mirror
        {
            float lg = ep[tid * 2] + ep[tid * 2 + 1];
            int il = tid >> 5, jj = tid & 31;
            int i_local = pass * 8 + il;
            g_logits[((size_t)b * NN + i0 + i_local) * NN + j0 + jj] = lg;
            tile[i_local * 33 + jj] = lg;
        }
        __syncthreads();
    }

    // coalesced mirror store (off-diagonal tiles only)
    if (ti != tj) {
        #pragma unroll
        for (int k = 0; k < 4; ++k) {
            int jj = (tid >> 5) + k * 8;     // j-local row
            int col = tid & 31;              // i-local
            g_logits[((size_t)b * NN + j0 + jj) * NN + i0 + col] =
                tile[col * 33 + jj];
        }
    }
}

// =====================================================================
// Kernel 1b2: softmax + agg + linear + BN + SELU + scores (fused)
// grid (16 ichunks, 16 b), block 256.
// =====================================================================
__global__ __launch_bounds__(256, 2)
void k1b2_fused(const float* __restrict__ x,
                const float* __restrict__ Wpwa, const float* __restrict__ bpwa,
                const float* __restrict__ Wpna, const float* __restrict__ bpna,
                const float* __restrict__ bnsc, const float* __restrict__ bnbi,
                const float* __restrict__ poolw, const float* __restrict__ poolb)
{
    __shared__ float xi_s[16 * 64];        // CTA's 16 x-rows
    __shared__ float aggs[16 * 64];
    __shared__ float A_s[NN];
    __shared__ float part[NN];
    __shared__ float red[8];
    __shared__ float Wa[64 * 68];          // Wpwa transposed [e][d], pad 68
    __shared__ float Wn[64 * 68];          // Wpna transposed
    __shared__ float prm[5 * 64 + 1];      // bpwa,bpna,bnsc,bnbi,poolw,poolb

    const int tid = threadIdx.x;
    const int lane = tid & 31, wid = tid >> 5;
    const int b  = blockIdx.y;
    const int i0 = blockIdx.x * 16;
    const float* xb = x + (size_t)b * NN * DD;

    // stage W transposed + params + x rows
    for (int t = tid; t < 4096; t += 256) {
        int d = t >> 6, e = t & 63;
        Wa[e * 68 + d] = Wpwa[t];
        Wn[e * 68 + d] = Wpna[t];
    }
    if (tid < 64) {
        prm[tid]       = bpwa[tid] + bpna[tid];
        prm[64 + tid]  = bnsc[tid] * rsqrtf(1.0f + 1e-5f);
        prm[128 + tid] = bnbi[tid];
        prm[192 + tid] = poolw[tid];
    }
    if (tid == 0) prm[320] = poolb[0];
    for (int t = tid; t < 1024; t += 256)
        xi_s[t] = xb[(size_t)i0 * DD + t];
    __syncthreads();

    // ---- phase 1: softmax + agg for 16 i ----
    for (int ii = 0; ii < 16; ++ii) {
        float logit = g_logits[((size_t)b * NN + i0 + ii) * NN + tid];

        float m = logit;
        #pragma unroll
        for (int o = 16; o; o >>= 1) m = fmaxf(m, __shfl_xor_sync(0xffffffffu, m, o));
        if (lane == 0) red[wid] = m;
        __syncthreads();
        m = red[0];
        #pragma unroll
        for (int w = 1; w < 8; ++w) m = fmaxf(m, red[w]);
        float ex = ex2f((logit - m) * LOG2E);
        float s = ex;
        #pragma unroll
        for (int o = 16; o; o >>= 1) s += __shfl_xor_sync(0xffffffffu, s, o);
        __syncthreads();
        if (lane == 0) red[wid] = s;
        __syncthreads();
        s = 0.f;
        #pragma unroll
        for (int w = 0; w < 8; ++w) s += red[w];
        A_s[tid] = ex / s;
        __syncthreads();

        {
            int q = tid >> 6, d = tid & 63;
            const float* xp = xb + (size_t)(q * 64) * DD + d;
            const float* Aq = A_s + q * 64;
            float pa = 0.f;
            #pragma unroll 8
            for (int jj = 0; jj < 64; ++jj) pa = fmaf(Aq[jj], xp[(size_t)jj * 64], pa);
            part[tid] = pa;
        }
        __syncthreads();
        if (tid < 64)
            aggs[ii * 64 + tid] = part[tid] + part[tid + 64] +
                                  part[tid + 128] + part[tid + 192];
        __syncthreads();
    }

    // ---- phase 2: h, BN, SELU, scores for 16 i ----
    const int e = tid & 63;
    const int ig4 = tid >> 6;            // 0..3
    const float4* war = (const float4*)(Wa + e * 68);
    const float4* wnr = (const float4*)(Wn + e * 68);
    const float bsum = prm[e];
    const float bnA = prm[64 + e], bnB = prm[128 + e], pw = prm[192 + e];

    #pragma unroll
    for (int k = 0; k < 4; ++k) {
        const int iloc = ig4 + k * 4;
        const float4* ag = (const float4*)(aggs + iloc * 64);
        const float4* xr = (const float4*)(xi_s + iloc * 64);
        float h = bsum;
        #pragma unroll 4
        for (int q = 0; q < 16; ++q) {
            float4 a = ag[q], wv = war[q];
            float4 xv = xr[q], nv = wnr[q];
            h = fmaf(a.x, wv.x, h); h = fmaf(a.y, wv.y, h);
            h = fmaf(a.z, wv.z, h); h = fmaf(a.w, wv.w, h);
            h = fmaf(xv.x, nv.x, h); h = fmaf(xv.y, nv.y, h);
            h = fmaf(xv.z, nv.z, h); h = fmaf(xv.w, nv.w, h);
        }
        h = h * bnA + bnB;
        h = 1.0507009873554805f *
            (h > 0.f ? h : 1.6732632423543772f * (__expf(h) - 1.f));
        g_h[((size_t)b * NN + i0 + iloc) * DD + e] = h;

        float r = h * pw;
        #pragma unroll
        for (int o = 16; o; o >>= 1) r += __shfl_xor_sync(0xffffffffu, r, o);
        if (lane == 0) red[wid] = r;
        __syncthreads();
        if (e == 0) {
            float z = red[ig4 * 2] + red[ig4 * 2 + 1] + prm[320];
            g_scores[b * NN + i0 + iloc] = 1.f / (1.f + __expf(-z));
        }
        __syncthreads();
    }
}

// =====================================================================
// Kernel 3: stable top-k + gather. grid (8 slices, 16 b), block 256.
// =====================================================================
__global__ __launch_bounds__(256)
void k3_topk(float* __restrict__ out)
{
    __shared__ float sc[NN];
    __shared__ int src[KTOP];
    const int tid = threadIdx.x;
    const int b = blockIdx.y;
    const int s0 = blockIdx.x * 16;      // row slice

    float s = g_scores[b * NN + tid];
    sc[tid] = s;
    __syncthreads();

    int rank = 0;
    #pragma unroll 8
    for (int j = 0; j < NN; ++j) {
        float sj = sc[j];
        rank += (sj > s) || (sj == s && j < tid);
    }
    if (rank < KTOP) src[rank] = tid;
    __syncthreads();

    // gather 16 rows, one float4 per thread
    {
        int r = s0 + (tid >> 4), q = tid & 15;
        int j = src[r];
        float w = sc[j];
        float4 v = ((const float4*)(g_h + ((size_t)b * NN + j) * DD))[q];
        v.x *= w; v.y *= w; v.z *= w; v.w *= w;
        ((float4*)(out + ((size_t)b * KTOP + r) * DD))[q] = v;
    }
}

// =====================================================================
extern "C" void kernel_launch(void* const* d_in, const int* in_sizes, int n_in,
                              void* d_out, int out_size)
{
    const float* x     = (const float*)d_in[0];
    const float* Watt  = (const float*)d_in[1];
    const float* batt  = (const float*)d_in[2];
    const float* attw  = (const float*)d_in[3];
    const float* Wpwa  = (const float*)d_in[4];
    const float* bpwa  = (const float*)d_in[5];
    const float* Wpna  = (const float*)d_in[6];
    const float* bpna  = (const float*)d_in[7];
    const float* bnsc  = (const float*)d_in[8];
    const float* bnbi  = (const float*)d_in[9];
    const float* poolw = (const float*)d_in[10];
    const float* poolb = (const float*)d_in[11];

    cudaFuncSetAttribute(k1a_logits,
                         cudaFuncAttributeMaxDynamicSharedMemorySize, SM_TOT1);

    dim3 ga(NPAIR, BB);
    k1a_logits<<<ga, 256, SM_TOT1>>>(x, Watt, batt, attw);
    dim3 gb(16, BB);
    k1b2_fused<<<gb, 256>>>(x, Wpwa, bpwa, Wpna, bpna,
                            bnsc, bnbi, poolw, poolb);
    dim3 gc(8, BB);
    k3_topk<<<gc, 256>>>((float*)d_out);
}

// round 8
// speedup vs baseline: 1.3524x; 1.3524x over previous
#include <cuda_runtime.h>
#include <math.h>
#include <stdint.h>

#define BB   16
#define NN   256
#define DD   64
#define KTOP 128
#define NT   8          // 256/32 tiles per dim
#define NPAIR 36        // NT*(NT+1)/2

// Scratch (no device allocations allowed)
__device__ float g_logits[BB * NN * NN];   // 4 MB
__device__ float g_h[BB * NN * DD];
__device__ float g_scores[BB * NN];

// ---------------- packed f32x2 helpers ----------------
__device__ __forceinline__ unsigned long long pack2f(float a, float b) {
    unsigned long long r;
    asm("mov.b64 %0, {%1, %2};" : "=l"(r) : "f"(a), "f"(b));
    return r;
}
__device__ __forceinline__ void fma2(unsigned long long& d,
                                     unsigned long long a,
                                     unsigned long long b) {
    asm("fma.rn.f32x2 %0, %1, %2, %0;" : "+l"(d) : "l"(a), "l"(b));
}
__device__ __forceinline__ float2 unpack2f(unsigned long long v) {
    float lo, hi;
    asm("mov.b64 {%0, %1}, %2;" : "=f"(lo), "=f"(hi) : "l"(v));
    float2 r; r.x = lo; r.y = hi;
    return r;
}
__device__ __forceinline__ float ex2f(float x) {
    float y; asm("ex2.approx.f32 %0, %1;" : "=f"(y) : "f"(x)); return y;
}
__device__ __forceinline__ float rcpf(float x) {
    float y; asm("rcp.approx.f32 %0, %1;" : "=f"(y) : "f"(x)); return y;
}

#define C2LOG2E 2.8853900817779268f   // 2*log2(e)
#define LOG2E   1.4426950408889634f

// ---------------- k1a smem layout (bytes) ----------------
// xip : [64][16] u64  i-pair scalars (32 i of CTA)       8192
// xj  : [64][36] f32  plain j values (pad 36)            9216
// w2  : [64][36] u64  W natural pairs; eh=1 half at +18 18432
// ep  : [8][64] f32   partial logits                     2048
// bw2 : 64 float2                                         512
// base: 2 f32 (+pad)                                       16
// tile: [32][33] f32                                     4224
#define SM_XIP  0
#define SM_XJ   8192
#define SM_W2   17408
#define SM_EP   35840
#define SM_BW   37888
#define SM_BASE 38400
#define SM_TILE 38416
#define SM_TOT1 (SM_TILE + 4224)

// =====================================================================
// Kernel 1a: symmetric logits. grid (36 tile-pairs, 16 b), block 256.
// Thread: ip = tid>>6 (i-pair), jl = (tid>>1)&31, eh = tid&1 (e-half).
// acc lanes = (e, e+1); 4 passes of 4 i-pairs (8 i) each.
// =====================================================================
__global__ __launch_bounds__(256, 2)
void k1a_logits(const float* __restrict__ x,
                const float* __restrict__ Watt,
                const float* __restrict__ batt_g,
                const float* __restrict__ attw_g)
{
    extern __shared__ char sm[];
    unsigned long long* xip = (unsigned long long*)(sm + SM_XIP);
    float* xjs  = (float*)(sm + SM_XJ);
    unsigned long long* w2 = (unsigned long long*)(sm + SM_W2);
    float*  ep   = (float*)(sm + SM_EP);
    float2* bw2  = (float2*)(sm + SM_BW);
    float*  base = (float*)(sm + SM_BASE);
    float*  tile = (float*)(sm + SM_TILE);

    const int tid = threadIdx.x;
    const int b   = blockIdx.y;

    // decode triangle tile pair
    int p = blockIdx.x, ti = 0;
    while (p >= NT - ti) { p -= NT - ti; ++ti; }
    const int tj = ti + p;
    const int i0 = ti * 32, j0 = tj * 32;

    const float* xb = x + (size_t)b * NN * DD;

    for (int t = tid; t < 1024; t += 256) {          // xip[d][ipg]
        int ipg = t >> 6, d = t & 63;
        float a = xb[(size_t)(i0 + 2 * ipg) * DD + d];
        float c = xb[(size_t)(i0 + 2 * ipg + 1) * DD + d];
        xip[d * 16 + ipg] = pack2f(a, c);
    }
    for (int t = tid; t < 2048; t += 256) {          // xj[d][j] plain
        int j = t >> 6, d = t & 63;
        xjs[d * 36 + j] = xb[(size_t)(j0 + j) * DD + d];
    }
    for (int t = tid; t < 2048; t += 256) {          // w2[d][slot] natural pairs
        int d = t >> 5, k = t & 31;                  // k = e-pair index
        float2 w = ((const float2*)Watt)[t];         // W[d][2k], W[d][2k+1]
        int slot = (k < 16) ? k : (k + 2);           // eh=1 half at +18
        w2[d * 36 + slot] = pack2f(w.x, w.y);
    }
    if (tid < 64) {
        float aww = attw_g[tid];
        bw2[tid] = make_float2(batt_g[tid] * C2LOG2E, -aww);
    }
    __syncthreads();
    if (tid < 2) {
        float s = 0.f;
        #pragma unroll
        for (int e = 0; e < 32; ++e) s -= bw2[tid * 32 + e].y;   // +aw
        base[tid] = 0.5f * s;
    }
    __syncthreads();

    const int ip = tid >> 6;            // 0..3
    const int jl = (tid >> 1) & 31;     // j lane
    const int eh = tid & 1;             // e half

    const float* xj_p = xjs + jl;
    const char* w_p = (const char*)(w2 + eh * 18);

    for (int pass = 0; pass < 4; ++pass) {
        unsigned long long acc0[16], acc1[16];
        #pragma unroll
        for (int k = 0; k < 16; ++k) { acc0[k] = 0ull; acc1[k] = 0ull; }

        const unsigned long long* xv = xip + (pass * 4 + ip);

        #pragma unroll 4
        for (int d = 0; d < 64; ++d) {
            float2 xi2 = unpack2f(xv[d * 16]);
            float xjv = xj_p[d * 36];
            float f0 = xi2.x * xjv, f1 = xi2.y * xjv;
            unsigned long long pp0 = pack2f(f0, f0);
            unsigned long long pp1 = pack2f(f1, f1);
            const ulonglong2* wr = (const ulonglong2*)(w_p + d * 288);
            #pragma unroll
            for (int h = 0; h < 8; ++h) {
                ulonglong2 wv = wr[h];
                fma2(acc0[2 * h + 0], pp0, wv.x);
                fma2(acc0[2 * h + 1], pp0, wv.y);
                fma2(acc1[2 * h + 0], pp1, wv.x);
                fma2(acc1[2 * h + 1], pp1, wv.y);
            }
        }

        // epilogue: tanh + dot(aw); lanes are (e, e+1)
        float pl0 = base[eh], pl1 = base[eh];
        const float2* bwh = bw2 + eh * 32;
        #pragma unroll
        for (int k = 0; k < 16; ++k) {
            float2 bc0 = bwh[2 * k], bc1 = bwh[2 * k + 1];
            float2 v0 = unpack2f(acc0[k]);
            float2 v1 = unpack2f(acc1[k]);
            float r00 = rcpf(ex2f(fmaf(v0.x, C2LOG2E, bc0.x)) + 1.f);
            float r01 = rcpf(ex2f(fmaf(v0.y, C2LOG2E, bc1.x)) + 1.f);
            float r10 = rcpf(ex2f(fmaf(v1.x, C2LOG2E, bc0.x)) + 1.f);
            float r11 = rcpf(ex2f(fmaf(v1.y, C2LOG2E, bc1.x)) + 1.f);
            pl0 = fmaf(bc0.y, r00, pl0);
            pl0 = fmaf(bc1.y, r01, pl0);
            pl1 = fmaf(bc0.y, r10, pl1);
            pl1 = fmaf(bc1.y, r11, pl1);
        }
        ep[(2 * ip + 0) * 64 + jl * 2 + eh] = pl0;
        ep[(2 * ip + 1) * 64 + jl * 2 + eh] = pl1;
        __syncthreads();

        // combine eh halves; direct store + stage for mirror
        {
            float lg = ep[tid * 2] + ep[tid * 2 + 1];
            int il = tid >> 5, jj = tid & 31;
            int i_local = pass * 8 + il;
            g_logits[((size_t)b * NN + i0 + i_local) * NN + j0 + jj] = lg;
            tile[i_local * 33 + jj] = lg;
        }
        __syncthreads();
    }

    // coalesced mirror store (off-diagonal tiles only)
    if (ti != tj) {
        #pragma unroll
        for (int k = 0; k < 4; ++k) {
            int jj = (tid >> 5) + k * 8;
            int col = tid & 31;
            g_logits[((size_t)b * NN + j0 + jj) * NN + i0 + col] =
                tile[col * 33 + jj];
        }
    }
}

// =====================================================================
// Kernel 1b2: softmax + agg + linear + BN + SELU + scores (fused)
// grid (16 ichunks, 16 b), block 256. Phase 1: 2 i per iteration.
// =====================================================================
__global__ __launch_bounds__(256, 2)
void k1b2_fused(const float* __restrict__ x,
                const float* __restrict__ Wpwa, const float* __restrict__ bpwa,
                const float* __restrict__ Wpna, const float* __restrict__ bpna,
                const float* __restrict__ bnsc, const float* __restrict__ bnbi,
                const float* __restrict__ poolw, const float* __restrict__ poolb)
{
    __shared__ float xi_s[16 * 64];
    __shared__ float aggs[16 * 64];
    __shared__ float A2[2 * NN];
    __shared__ float part2[2 * 128];
    __shared__ float redM[8];
    __shared__ float redS[8];
    __shared__ float red[8];
    __shared__ float Wa[64 * 68];
    __shared__ float Wn[64 * 68];
    __shared__ float prm[5 * 64 + 1];

    const int tid = threadIdx.x;
    const int lane = tid & 31, wid = tid >> 5;
    const int b  = blockIdx.y;
    const int i0 = blockIdx.x * 16;
    const float* xb = x + (size_t)b * NN * DD;

    for (int t = tid; t < 4096; t += 256) {
        int d = t >> 6, e = t & 63;
        Wa[e * 68 + d] = Wpwa[t];
        Wn[e * 68 + d] = Wpna[t];
    }
    if (tid < 64) {
        prm[tid]       = bpwa[tid] + bpna[tid];
        prm[64 + tid]  = bnsc[tid] * rsqrtf(1.0f + 1e-5f);
        prm[128 + tid] = bnbi[tid];
        prm[192 + tid] = poolw[tid];
    }
    if (tid == 0) prm[320] = poolb[0];
    for (int t = tid; t < 1024; t += 256)
        xi_s[t] = xb[(size_t)i0 * DD + t];
    __syncthreads();

    // ---- phase 1: softmax + agg, 2 i per iteration ----
    const int h = tid >> 7;            // half 0/1
    const int t7 = tid & 127;
    for (int ii = 0; ii < 8; ++ii) {
        const int iloc = 2 * ii + h;
        const float* lrow = g_logits + ((size_t)b * NN + i0 + iloc) * NN;
        float l0 = lrow[t7], l1 = lrow[t7 + 128];

        float m = fmaxf(l0, l1);
        #pragma unroll
        for (int o = 16; o; o >>= 1) m = fmaxf(m, __shfl_xor_sync(0xffffffffu, m, o));
        if (lane == 0) redM[wid] = m;
        __syncthreads();
        m = fmaxf(fmaxf(redM[h * 4 + 0], redM[h * 4 + 1]),
                  fmaxf(redM[h * 4 + 2], redM[h * 4 + 3]));
        float e0 = ex2f((l0 - m) * LOG2E);
        float e1 = ex2f((l1 - m) * LOG2E);
        float s = e0 + e1;
        #pragma unroll
        for (int o = 16; o; o >>= 1) s += __shfl_xor_sync(0xffffffffu, s, o);
        if (lane == 0) redS[wid] = s;
        __syncthreads();
        s = redS[h * 4 + 0] + redS[h * 4 + 1] + redS[h * 4 + 2] + redS[h * 4 + 3];
        float inv = 1.f / s;
        A2[h * NN + t7] = e0 * inv;
        A2[h * NN + t7 + 128] = e1 * inv;
        __syncthreads();

        // agg: each half-CTA handles its i; q = t7>>6 picks 128-j range
        {
            int q = t7 >> 6, d = t7 & 63;
            const float* xp = xb + (size_t)(q * 128) * DD + d;
            const float* Aq = A2 + h * NN + q * 128;
            float pa = 0.f;
            #pragma unroll 8
            for (int jj = 0; jj < 128; ++jj) pa = fmaf(Aq[jj], xp[(size_t)jj * 64], pa);
            part2[h * 128 + q * 64 + d] = pa;
        }
        __syncthreads();
        if (tid < 128) {
            int h2 = tid >> 6, d = tid & 63;
            aggs[(2 * ii + h2) * 64 + d] =
                part2[h2 * 128 + d] + part2[h2 * 128 + 64 + d];
        }
        __syncthreads();
    }

    // ---- phase 2: h, BN, SELU, scores for 16 i ----
    const int e = tid & 63;
    const int ig4 = tid >> 6;
    const float4* war = (const float4*)(Wa + e * 68);
    const float4* wnr = (const float4*)(Wn + e * 68);
    const float bsum = prm[e];
    const float bnA = prm[64 + e], bnB = prm[128 + e], pw = prm[192 + e];

    #pragma unroll
    for (int k = 0; k < 4; ++k) {
        const int iloc = ig4 + k * 4;
        const float4* ag = (const float4*)(aggs + iloc * 64);
        const float4* xr = (const float4*)(xi_s + iloc * 64);
        float hv = bsum;
        #pragma unroll 4
        for (int q = 0; q < 16; ++q) {
            float4 a = ag[q], wv = war[q];
            float4 xv = xr[q], nv = wnr[q];
            hv = fmaf(a.x, wv.x, hv); hv = fmaf(a.y, wv.y, hv);
            hv = fmaf(a.z, wv.z, hv); hv = fmaf(a.w, wv.w, hv);
            hv = fmaf(xv.x, nv.x, hv); hv = fmaf(xv.y, nv.y, hv);
            hv = fmaf(xv.z, nv.z, hv); hv = fmaf(xv.w, nv.w, hv);
        }
        hv = hv * bnA + bnB;
        hv = 1.0507009873554805f *
             (hv > 0.f ? hv : 1.6732632423543772f * (__expf(hv) - 1.f));
        g_h[((size_t)b * NN + i0 + iloc) * DD + e] = hv;

        float r = hv * pw;
        #pragma unroll
        for (int o = 16; o; o >>= 1) r += __shfl_xor_sync(0xffffffffu, r, o);
        if (lane == 0) red[wid] = r;
        __syncthreads();
        if (e == 0) {
            float z = red[ig4 * 2] + red[ig4 * 2 + 1] + prm[320];
            g_scores[b * NN + i0 + iloc] = 1.f / (1.f + __expf(-z));
        }
        __syncthreads();
    }
}

// =====================================================================
// Kernel 3: stable top-k + gather. grid (8 slices, 16 b), block 256.
// =====================================================================
__global__ __launch_bounds__(256)
void k3_topk(float* __restrict__ out)
{
    __shared__ float sc[NN];
    __shared__ int src[KTOP];
    const int tid = threadIdx.x;
    const int b = blockIdx.y;
    const int s0 = blockIdx.x * 16;

    float s = g_scores[b * NN + tid];
    sc[tid] = s;
    __syncthreads();

    int rank = 0;
    #pragma unroll 8
    for (int j = 0; j < NN; ++j) {
        float sj = sc[j];
        rank += (sj > s) || (sj == s && j < tid);
    }
    if (rank < KTOP) src[rank] = tid;
    __syncthreads();

    {
        int r = s0 + (tid >> 4), q = tid & 15;
        int j = src[r];
        float w = sc[j];
        float4 v = ((const float4*)(g_h + ((size_t)b * NN + j) * DD))[q];
        v.x *= w; v.y *= w; v.z *= w; v.w *= w;
        ((float4*)(out + ((size_t)b * KTOP + r) * DD))[q] = v;
    }
}

// =====================================================================
extern "C" void kernel_launch(void* const* d_in, const int* in_sizes, int n_in,
                              void* d_out, int out_size)
{
    const float* x     = (const float*)d_in[0];
    const float* Watt  = (const float*)d_in[1];
    const float* batt  = (const float*)d_in[2];
    const float* attw  = (const float*)d_in[3];
    const float* Wpwa  = (const float*)d_in[4];
    const float* bpwa  = (const float*)d_in[5];
    const float* Wpna  = (const float*)d_in[6];
    const float* bpna  = (const float*)d_in[7];
    const float* bnsc  = (const float*)d_in[8];
    const float* bnbi  = (const float*)d_in[9];
    const float* poolw = (const float*)d_in[10];
    const float* poolb = (const float*)d_in[11];

    cudaFuncSetAttribute(k1a_logits,
                         cudaFuncAttributeMaxDynamicSharedMemorySize, SM_TOT1);

    dim3 ga(NPAIR, BB);
    k1a_logits<<<ga, 256, SM_TOT1>>>(x, Watt, batt, attw);
    dim3 gb(16, BB);
    k1b2_fused<<<gb, 256>>>(x, Wpwa, bpwa, Wpna, bpna,
                            bnsc, bnbi, poolw, poolb);
    dim3 gc(8, BB);
    k3_topk<<<gc, 256>>>((float*)d_out);
}

// round 9
// speedup vs baseline: 1.4410x; 1.0655x over previous
#include <cuda_runtime.h>
#include <math.h>
#include <stdint.h>

#define BB   16
#define NN   256
#define DD   64
#define KTOP 128
#define NT   8          // 256/32 tiles per dim
#define NPAIR 36        // NT*(NT+1)/2

// Scratch (no device allocations allowed)
__device__ float g_logits[BB * NN * NN];   // 4 MB
__device__ float g_h[BB * NN * DD];
__device__ float g_scores[BB * NN];

// ---------------- packed f32x2 helpers ----------------
__device__ __forceinline__ unsigned long long pack2f(float a, float b) {
    unsigned long long r;
    asm("mov.b64 %0, {%1, %2};" : "=l"(r) : "f"(a), "f"(b));
    return r;
}
__device__ __forceinline__ void fma2(unsigned long long& d,
                                     unsigned long long a,
                                     unsigned long long b) {
    asm("fma.rn.f32x2 %0, %1, %2, %0;" : "+l"(d) : "l"(a), "l"(b));
}
__device__ __forceinline__ float2 unpack2f(unsigned long long v) {
    float lo, hi;
    asm("mov.b64 {%0, %1}, %2;" : "=f"(lo), "=f"(hi) : "l"(v));
    float2 r; r.x = lo; r.y = hi;
    return r;
}
__device__ __forceinline__ float ex2f(float x) {
    float y; asm("ex2.approx.f32 %0, %1;" : "=f"(y) : "f"(x)); return y;
}
__device__ __forceinline__ float rcpf(float x) {
    float y; asm("rcp.approx.f32 %0, %1;" : "=f"(y) : "f"(x)); return y;
}

#define C2LOG2E 2.8853900817779268f   // 2*log2(e)
#define LOG2E   1.4426950408889634f

// ---------------- k1a smem layout (bytes) ----------------
#define SM_XIP  0                      // [64][16] u64  i-pair scalars
#define SM_XJ   8192                   // [64][36] f32  plain j values
#define SM_W2   17408                  // [64][36] u64  W natural pairs
#define SM_EP   35840                  // [32][68] f32  partial logits (8704)
#define SM_BW   44544                  // 64 float2
#define SM_BASE 45056                  // 2 f32 (+pad)
#define SM_TILE 45072                  // [32][33] f32
#define SM_TOT1 (SM_TILE + 4224)       // 49296

// =====================================================================
// Kernel 1a: symmetric logits. grid (36 tile-pairs, 16 b), block 256.
// Sync-free pass loop; single batched combine at the end.
// =====================================================================
__global__ __launch_bounds__(256, 2)
void k1a_logits(const float* __restrict__ x,
                const float* __restrict__ Watt,
                const float* __restrict__ batt_g,
                const float* __restrict__ attw_g)
{
    extern __shared__ char sm[];
    unsigned long long* xip = (unsigned long long*)(sm + SM_XIP);
    float* xjs  = (float*)(sm + SM_XJ);
    unsigned long long* w2 = (unsigned long long*)(sm + SM_W2);
    float*  ep   = (float*)(sm + SM_EP);
    float2* bw2  = (float2*)(sm + SM_BW);
    float*  base = (float*)(sm + SM_BASE);
    float*  tile = (float*)(sm + SM_TILE);

    const int tid = threadIdx.x;
    const int b   = blockIdx.y;

    // decode triangle tile pair
    int p = blockIdx.x, ti = 0;
    while (p >= NT - ti) { p -= NT - ti; ++ti; }
    const int tj = ti + p;
    const int i0 = ti * 32, j0 = tj * 32;

    const float* xb = x + (size_t)b * NN * DD;

    for (int t = tid; t < 1024; t += 256) {          // xip[d][ipg]
        int ipg = t >> 6, d = t & 63;
        float a = xb[(size_t)(i0 + 2 * ipg) * DD + d];
        float c = xb[(size_t)(i0 + 2 * ipg + 1) * DD + d];
        xip[d * 16 + ipg] = pack2f(a, c);
    }
    for (int t = tid; t < 2048; t += 256) {          // xj[d][j] plain
        int j = t >> 6, d = t & 63;
        xjs[d * 36 + j] = xb[(size_t)(j0 + j) * DD + d];
    }
    for (int t = tid; t < 2048; t += 256) {          // w2[d][slot] natural pairs
        int d = t >> 5, k = t & 31;
        float2 w = ((const float2*)Watt)[t];
        int slot = (k < 16) ? k : (k + 2);           // eh=1 half at +18
        w2[d * 36 + slot] = pack2f(w.x, w.y);
    }
    if (tid < 64) {
        float aww = attw_g[tid];
        bw2[tid] = make_float2(batt_g[tid] * C2LOG2E, -aww);
    }
    __syncthreads();
    if (tid < 2) {
        float s = 0.f;
        #pragma unroll
        for (int e = 0; e < 32; ++e) s -= bw2[tid * 32 + e].y;   // +aw
        base[tid] = 0.5f * s;
    }
    __syncthreads();

    const int ip = tid >> 6;            // 0..3
    const int jl = (tid >> 1) & 31;     // j lane
    const int eh = tid & 1;             // e half

    const float* xj_p = xjs + jl;
    const char* w_p = (const char*)(w2 + eh * 18);
    const float bs = base[eh];
    const float2* bwh = bw2 + eh * 32;

    for (int pass = 0; pass < 4; ++pass) {
        unsigned long long acc0[16], acc1[16];
        #pragma unroll
        for (int k = 0; k < 16; ++k) { acc0[k] = 0ull; acc1[k] = 0ull; }

        const unsigned long long* xv = xip + (pass * 4 + ip);

        #pragma unroll 4
        for (int d = 0; d < 64; ++d) {
            float2 xi2 = unpack2f(xv[d * 16]);
            float xjv = xj_p[d * 36];
            float f0 = xi2.x * xjv, f1 = xi2.y * xjv;
            unsigned long long pp0 = pack2f(f0, f0);
            unsigned long long pp1 = pack2f(f1, f1);
            const ulonglong2* wr = (const ulonglong2*)(w_p + d * 288);
            #pragma unroll
            for (int h = 0; h < 8; ++h) {
                ulonglong2 wv = wr[h];
                fma2(acc0[2 * h + 0], pp0, wv.x);
                fma2(acc0[2 * h + 1], pp0, wv.y);
                fma2(acc1[2 * h + 0], pp1, wv.x);
                fma2(acc1[2 * h + 1], pp1, wv.y);
            }
        }

        // epilogue: paired-rcp tanh dot(aw); acc lanes = (e, e+1)
        float pl0 = bs, pl1 = bs;
        #pragma unroll
        for (int k = 0; k < 16; ++k) {
            float2 bc0 = bwh[2 * k], bc1 = bwh[2 * k + 1];
            float2 v0 = unpack2f(acc0[k]);
            float2 v1 = unpack2f(acc1[k]);
            // i-lane 0: aw0*r0+aw1*r1 = -(bc0.y*B + bc1.y*A)*rcp(A*B)
            float y00 = fminf(fmaf(v0.x, C2LOG2E, bc0.x), 60.f);
            float y01 = fminf(fmaf(v0.y, C2LOG2E, bc1.x), 60.f);
            float A0 = ex2f(y00) + 1.f, B0 = ex2f(y01) + 1.f;
            float N0 = bc0.y * B0; N0 = fmaf(bc1.y, A0, N0);
            pl0 = fmaf(N0, rcpf(A0 * B0), pl0);
            // i-lane 1
            float y10 = fminf(fmaf(v1.x, C2LOG2E, bc0.x), 60.f);
            float y11 = fminf(fmaf(v1.y, C2LOG2E, bc1.x), 60.f);
            float A1 = ex2f(y10) + 1.f, B1 = ex2f(y11) + 1.f;
            float N1 = bc0.y * B1; N1 = fmaf(bc1.y, A1, N1);
            pl1 = fmaf(N1, rcpf(A1 * B1), pl1);
        }
        {
            int r0 = (pass * 4 + ip) * 2;
            ep[r0 * 68 + jl * 2 + eh] = pl0;
            ep[(r0 + 1) * 68 + jl * 2 + eh] = pl1;
        }
        // NO sync: each pass writes a disjoint ep region
    }
    __syncthreads();

    // combine eh halves for all 32 rows; store direct + stage tile
    {
        int i_loc = tid >> 3, jq = tid & 7;
        const float* er = ep + i_loc * 68 + jq * 8;
        float4 lo = *(const float4*)(er);
        float4 hi = *(const float4*)(er + 4);
        float4 lg = make_float4(lo.x + lo.y, lo.z + lo.w,
                                hi.x + hi.y, hi.z + hi.w);
        *(float4*)(&g_logits[((size_t)b * NN + i0 + i_loc) * NN + j0 + jq * 4]) = lg;
        float* tr = tile + i_loc * 33 + jq * 4;
        tr[0] = lg.x; tr[1] = lg.y; tr[2] = lg.z; tr[3] = lg.w;
    }
    __syncthreads();

    // coalesced mirror store (off-diagonal tiles only)
    if (ti != tj) {
        #pragma unroll
        for (int k = 0; k < 4; ++k) {
            int jj = (tid >> 5) + k * 8;
            int col = tid & 31;
            g_logits[((size_t)b * NN + j0 + jj) * NN + i0 + col] =
                tile[col * 33 + jj];
        }
    }
}

// ---------------- k1b2 smem layout (bytes) ----------------
#define SMB_XS  0                      // 256*64 f32 = 65536
#define SMB_WA  65536                  // [d][e] 64*64 f32 = 16384
#define SMB_WN  81920                  // 16384
#define SMB_AG  98304                  // [32][64] f32 = 8192
#define SMB_PRM 106496                 // 5*64+8 f32
#define SMB_TOT (106496 + 1312)

// =====================================================================
// Kernel 1b2: softmax + agg + linear + BN + SELU + scores.
// grid (8, 16), block 256 (8 warps). Warp owns 4 i's; barrier-free
// after staging (warp-synchronous shuffles + own smem regions only).
// =====================================================================
__global__ __launch_bounds__(256, 2)
void k1b2_fused(const float* __restrict__ x,
                const float* __restrict__ Wpwa, const float* __restrict__ bpwa,
                const float* __restrict__ Wpna, const float* __restrict__ bpna,
                const float* __restrict__ bnsc, const float* __restrict__ bnbi,
                const float* __restrict__ poolw, const float* __restrict__ poolb)
{
    extern __shared__ char sm2[];
    float* xs   = (float*)(sm2 + SMB_XS);
    float* Wa   = (float*)(sm2 + SMB_WA);
    float* Wn   = (float*)(sm2 + SMB_WN);
    float* aggs = (float*)(sm2 + SMB_AG);
    float* prm  = (float*)(sm2 + SMB_PRM);

    const int tid = threadIdx.x;
    const int lane = tid & 31, w = tid >> 5;
    const int b  = blockIdx.y;
    const int i0 = blockIdx.x * 32;
    const float* xb = x + (size_t)b * NN * DD;

    // stage x_b (64KB), W's (natural [d][e] layout), params
    for (int t = tid; t < 4096; t += 256)
        ((float4*)xs)[t] = ((const float4*)xb)[t];
    for (int t = tid; t < 1024; t += 256) {
        ((float4*)Wa)[t] = ((const float4*)Wpwa)[t];
        ((float4*)Wn)[t] = ((const float4*)Wpna)[t];
    }
    if (tid < 64) {
        prm[tid]       = bpwa[tid] + bpna[tid];
        prm[64 + tid]  = bnsc[tid] * rsqrtf(1.0f + 1e-5f);
        prm[128 + tid] = bnbi[tid];
        prm[192 + tid] = poolw[tid];
    }
    if (tid == 0) prm[320] = poolb[0];
    __syncthreads();

    const int d0 = lane * 2;
    const int e0 = lane * 2;

    for (int c = 0; c < 4; ++c) {
        const int iL = w * 4 + c;          // local 0..31
        const int ig = i0 + iL;            // global node

        // ---- softmax over 256 j (warp-only) ----
        const float* lrow = g_logits + ((size_t)b * NN + ig) * NN;
        float4 va = ((const float4*)lrow)[lane];
        float4 vb = ((const float4*)lrow)[32 + lane];
        float av[8] = { va.x, va.y, va.z, va.w, vb.x, vb.y, vb.z, vb.w };

        float m = av[0];
        #pragma unroll
        for (int k = 1; k < 8; ++k) m = fmaxf(m, av[k]);
        #pragma unroll
        for (int o = 16; o; o >>= 1) m = fmaxf(m, __shfl_xor_sync(0xffffffffu, m, o));

        float s = 0.f;
        #pragma unroll
        for (int k = 0; k < 8; ++k) { av[k] = ex2f((av[k] - m) * LOG2E); s += av[k]; }
        #pragma unroll
        for (int o = 16; o; o >>= 1) s += __shfl_xor_sync(0xffffffffu, s, o);
        float inv = 1.f / s;
        #pragma unroll
        for (int k = 0; k < 8; ++k) av[k] *= inv;

        // ---- agg[d0,d0+1] = sum_j A[j] * x[j][d] (smem, shuffle bcast) ----
        float ax0 = 0.f, ay0 = 0.f, ax1 = 0.f, ay1 = 0.f;
        #pragma unroll 4
        for (int src = 0; src < 32; ++src) {
            #pragma unroll
            for (int k = 0; k < 8; ++k) {
                float A = __shfl_sync(0xffffffffu, av[k], src);
                int j = src * 4 + (k & 3) + ((k & 4) << 5);
                float2 xv = *(const float2*)(xs + j * 64 + d0);
                if (k < 4) { ax0 = fmaf(A, xv.x, ax0); ay0 = fmaf(A, xv.y, ay0); }
                else       { ax1 = fmaf(A, xv.x, ax1); ay1 = fmaf(A, xv.y, ay1); }
            }
        }
        *(float2*)(aggs + iL * 64 + d0) = make_float2(ax0 + ax1, ay0 + ay1);
        __syncwarp();

        // ---- linear + BN + SELU + score (warp-only) ----
        float ha0 = 0.f, ha1 = 0.f, hn0 = 0.f, hn1 = 0.f;
        #pragma unroll 8
        for (int d = 0; d < 64; ++d) {
            float ad = aggs[iL * 64 + d];
            float xd = xs[ig * 64 + d];
            float2 wa = *(const float2*)(Wa + d * 64 + e0);
            float2 wn = *(const float2*)(Wn + d * 64 + e0);
            ha0 = fmaf(ad, wa.x, ha0); ha1 = fmaf(ad, wa.y, ha1);
            hn0 = fmaf(xd, wn.x, hn0); hn1 = fmaf(xd, wn.y, hn1);
        }
        float h0 = ha0 + hn0 + prm[e0];
        float h1 = ha1 + hn1 + prm[e0 + 1];
        h0 = h0 * prm[64 + e0] + prm[128 + e0];
        h1 = h1 * prm[64 + e0 + 1] + prm[128 + e0 + 1];
        h0 = 1.0507009873554805f *
             (h0 > 0.f ? h0 : 1.6732632423543772f * (__expf(h0) - 1.f));
        h1 = 1.0507009873554805f *
             (h1 > 0.f ? h1 : 1.6732632423543772f * (__expf(h1) - 1.f));
        *(float2*)(g_h + ((size_t)b * NN + ig) * DD + e0) = make_float2(h0, h1);

        float r = h0 * prm[192 + e0] + h1 * prm[192 + e0 + 1];
        #pragma unroll
        for (int o = 16; o; o >>= 1) r += __shfl_xor_sync(0xffffffffu, r, o);
        if (lane == 0)
            g_scores[b * NN + ig] = 1.f / (1.f + __expf(-(r + prm[320])));
    }
}

// =====================================================================
// Kernel 3: stable top-k + gather. grid (8 slices, 16 b), block 256.
// =====================================================================
__global__ __launch_bounds__(256)
void k3_topk(float* __restrict__ out)
{
    __shared__ float sc[NN];
    __shared__ int src[KTOP];
    const int tid = threadIdx.x;
    const int b = blockIdx.y;
    const int s0 = blockIdx.x * 16;

    float s = g_scores[b * NN + tid];
    sc[tid] = s;
    __syncthreads();

    int rank = 0;
    #pragma unroll 8
    for (int j = 0; j < NN; ++j) {
        float sj = sc[j];
        rank += (sj > s) || (sj == s && j < tid);
    }
    if (rank < KTOP) src[rank] = tid;
    __syncthreads();

    {
        int r = s0 + (tid >> 4), q = tid & 15;
        int j = src[r];
        float w = sc[j];
        float4 v = ((const float4*)(g_h + ((size_t)b * NN + j) * DD))[q];
        v.x *= w; v.y *= w; v.z *= w; v.w *= w;
        ((float4*)(out + ((size_t)b * KTOP + r) * DD))[q] = v;
    }
}

// =====================================================================
extern "C" void kernel_launch(void* const* d_in, const int* in_sizes, int n_in,
                              void* d_out, int out_size)
{
    const float* x     = (const float*)d_in[0];
    const float* Watt  = (const float*)d_in[1];
    const float* batt  = (const float*)d_in[2];
    const float* attw  = (const float*)d_in[3];
    const float* Wpwa  = (const float*)d_in[4];
    const float* bpwa  = (const float*)d_in[5];
    const float* Wpna  = (const float*)d_in[6];
    const float* bpna  = (const float*)d_in[7];
    const float* bnsc  = (const float*)d_in[8];
    const float* bnbi  = (const float*)d_in[9];
    const float* poolw = (const float*)d_in[10];
    const float* poolb = (const float*)d_in[11];

    cudaFuncSetAttribute(k1a_logits,
                         cudaFuncAttributeMaxDynamicSharedMemorySize, SM_TOT1);
    cudaFuncSetAttribute(k1b2_fused,
                         cudaFuncAttributeMaxDynamicSharedMemorySize, SMB_TOT);

    dim3 ga(NPAIR, BB);
    k1a_logits<<<ga, 256, SM_TOT1>>>(x, Watt, batt, attw);
    dim3 gb(8, BB);
    k1b2_fused<<<gb, 256, SMB_TOT>>>(x, Wpwa, bpwa, Wpna, bpna,
                                     bnsc, bnbi, poolw, poolb);
    dim3 gc(8, BB);
    k3_topk<<<gc, 256>>>((float*)d_out);
}

// round 10
// speedup vs baseline: 1.5410x; 1.0694x over previous
#include <cuda_runtime.h>
#include <math.h>
#include <stdint.h>

#define BB   16
#define NN   256
#define DD   64
#define KTOP 128
#define NT   8          // 256/32 tiles per dim
#define NPAIR 36        // NT*(NT+1)/2

// Scratch (no device allocations allowed)
__device__ float g_logits[BB * NN * NN];   // 4 MB
__device__ float g_h[BB * NN * DD];
__device__ float g_scores[BB * NN];

// ---------------- packed f32x2 helpers ----------------
__device__ __forceinline__ unsigned long long pack2f(float a, float b) {
    unsigned long long r;
    asm("mov.b64 %0, {%1, %2};" : "=l"(r) : "f"(a), "f"(b));
    return r;
}
__device__ __forceinline__ void fma2(unsigned long long& d,
                                     unsigned long long a,
                                     unsigned long long b) {
    asm("fma.rn.f32x2 %0, %1, %2, %0;" : "+l"(d) : "l"(a), "l"(b));
}
__device__ __forceinline__ float2 unpack2f(unsigned long long v) {
    float lo, hi;
    asm("mov.b64 {%0, %1}, %2;" : "=f"(lo), "=f"(hi) : "l"(v));
    float2 r; r.x = lo; r.y = hi;
    return r;
}
__device__ __forceinline__ float ex2f(float x) {
    float y; asm("ex2.approx.f32 %0, %1;" : "=f"(y) : "f"(x)); return y;
}
__device__ __forceinline__ float rcpf(float x) {
    float y; asm("rcp.approx.f32 %0, %1;" : "=f"(y) : "f"(x)); return y;
}

#define C2LOG2E 2.8853900817779268f   // 2*log2(e)
#define LOG2E   1.4426950408889634f

// ---------------- k1a smem layout (bytes) ----------------
// xip : [64][16] u64  i-pair scalars (32 i of CTA)       8192
// xj  : [64][36] f32  plain j values (pad 36)            9216
// w2  : [64][36] u64  W natural pairs; eh=1 half at +18 18432
// ep  : [8][64] f32   partial logits                     2048
// bw2 : 64 float2                                         512
// base: 2 f32 (+pad)                                       16
// tile: [32][33] f32                                     4224
#define SM_XIP  0
#define SM_XJ   8192
#define SM_W2   17408
#define SM_EP   35840
#define SM_BW   37888
#define SM_BASE 38400
#define SM_TILE 38416
#define SM_TOT1 (SM_TILE + 4224)

// =====================================================================
// Kernel 1a: symmetric logits. grid (36 tile-pairs, 16 b), block 256.
// Thread: ip = tid>>6 (i-pair), jl = (tid>>1)&31, eh = tid&1 (e-half).
// acc lanes = (e, e+1); 4 passes of 4 i-pairs (8 i) each.
// (round-8 structure: per-pass syncs, one rcp per tanh — measured best)
// =====================================================================
__global__ __launch_bounds__(256, 2)
void k1a_logits(const float* __restrict__ x,
                const float* __restrict__ Watt,
                const float* __restrict__ batt_g,
                const float* __restrict__ attw_g)
{
    extern __shared__ char sm[];
    unsigned long long* xip = (unsigned long long*)(sm + SM_XIP);
    float* xjs  = (float*)(sm + SM_XJ);
    unsigned long long* w2 = (unsigned long long*)(sm + SM_W2);
    float*  ep   = (float*)(sm + SM_EP);
    float2* bw2  = (float2*)(sm + SM_BW);
    float*  base = (float*)(sm + SM_BASE);
    float*  tile = (float*)(sm + SM_TILE);

    const int tid = threadIdx.x;
    const int b   = blockIdx.y;

    // decode triangle tile pair
    int p = blockIdx.x, ti = 0;
    while (p >= NT - ti) { p -= NT - ti; ++ti; }
    const int tj = ti + p;
    const int i0 = ti * 32, j0 = tj * 32;

    const float* xb = x + (size_t)b * NN * DD;

    for (int t = tid; t < 1024; t += 256) {          // xip[d][ipg]
        int ipg = t >> 6, d = t & 63;
        float a = xb[(size_t)(i0 + 2 * ipg) * DD + d];
        float c = xb[(size_t)(i0 + 2 * ipg + 1) * DD + d];
        xip[d * 16 + ipg] = pack2f(a, c);
    }
    for (int t = tid; t < 2048; t += 256) {          // xj[d][j] plain
        int j = t >> 6, d = t & 63;
        xjs[d * 36 + j] = xb[(size_t)(j0 + j) * DD + d];
    }
    for (int t = tid; t < 2048; t += 256) {          // w2[d][slot] natural pairs
        int d = t >> 5, k = t & 31;                  // k = e-pair index
        float2 w = ((const float2*)Watt)[t];         // W[d][2k], W[d][2k+1]
        int slot = (k < 16) ? k : (k + 2);           // eh=1 half at +18
        w2[d * 36 + slot] = pack2f(w.x, w.y);
    }
    if (tid < 64) {
        float aww = attw_g[tid];
        bw2[tid] = make_float2(batt_g[tid] * C2LOG2E, -aww);
    }
    __syncthreads();
    if (tid < 2) {
        float s = 0.f;
        #pragma unroll
        for (int e = 0; e < 32; ++e) s -= bw2[tid * 32 + e].y;   // +aw
        base[tid] = 0.5f * s;
    }
    __syncthreads();

    const int ip = tid >> 6;            // 0..3
    const int jl = (tid >> 1) & 31;     // j lane
    const int eh = tid & 1;             // e half

    const float* xj_p = xjs + jl;
    const char* w_p = (const char*)(w2 + eh * 18);

    for (int pass = 0; pass < 4; ++pass) {
        unsigned long long acc0[16], acc1[16];
        #pragma unroll
        for (int k = 0; k < 16; ++k) { acc0[k] = 0ull; acc1[k] = 0ull; }

        const unsigned long long* xv = xip + (pass * 4 + ip);

        #pragma unroll 4
        for (int d = 0; d < 64; ++d) {
            float2 xi2 = unpack2f(xv[d * 16]);
            float xjv = xj_p[d * 36];
            float f0 = xi2.x * xjv, f1 = xi2.y * xjv;
            unsigned long long pp0 = pack2f(f0, f0);
            unsigned long long pp1 = pack2f(f1, f1);
            const ulonglong2* wr = (const ulonglong2*)(w_p + d * 288);
            #pragma unroll
            for (int h = 0; h < 8; ++h) {
                ulonglong2 wv = wr[h];
                fma2(acc0[2 * h + 0], pp0, wv.x);
                fma2(acc0[2 * h + 1], pp0, wv.y);
                fma2(acc1[2 * h + 0], pp1, wv.x);
                fma2(acc1[2 * h + 1], pp1, wv.y);
            }
        }

        // epilogue: tanh + dot(aw); lanes are (e, e+1)
        float pl0 = base[eh], pl1 = base[eh];
        const float2* bwh = bw2 + eh * 32;
        #pragma unroll
        for (int k = 0; k < 16; ++k) {
            float2 bc0 = bwh[2 * k], bc1 = bwh[2 * k + 1];
            float2 v0 = unpack2f(acc0[k]);
            float2 v1 = unpack2f(acc1[k]);
            float r00 = rcpf(ex2f(fmaf(v0.x, C2LOG2E, bc0.x)) + 1.f);
            float r01 = rcpf(ex2f(fmaf(v0.y, C2LOG2E, bc1.x)) + 1.f);
            float r10 = rcpf(ex2f(fmaf(v1.x, C2LOG2E, bc0.x)) + 1.f);
            float r11 = rcpf(ex2f(fmaf(v1.y, C2LOG2E, bc1.x)) + 1.f);
            pl0 = fmaf(bc0.y, r00, pl0);
            pl0 = fmaf(bc1.y, r01, pl0);
            pl1 = fmaf(bc0.y, r10, pl1);
            pl1 = fmaf(bc1.y, r11, pl1);
        }
        ep[(2 * ip + 0) * 64 + jl * 2 + eh] = pl0;
        ep[(2 * ip + 1) * 64 + jl * 2 + eh] = pl1;
        __syncthreads();

        // combine eh halves; direct store + stage for mirror
        {
            float lg = ep[tid * 2] + ep[tid * 2 + 1];
            int il = tid >> 5, jj = tid & 31;
            int i_local = pass * 8 + il;
            g_logits[((size_t)b * NN + i0 + i_local) * NN + j0 + jj] = lg;
            tile[i_local * 33 + jj] = lg;
        }
        __syncthreads();
    }

    // coalesced mirror store (off-diagonal tiles only)
    if (ti != tj) {
        #pragma unroll
        for (int k = 0; k < 4; ++k) {
            int jj = (tid >> 5) + k * 8;
            int col = tid & 31;
            g_logits[((size_t)b * NN + j0 + jj) * NN + i0 + col] =
                tile[col * 33 + jj];
        }
    }
}

// ---------------- k1b2 smem layout (bytes) ----------------
#define SMB_XS  0                      // 256*64 f32 = 65536
#define SMB_WA  65536                  // [d][e] 64*64 f32 = 16384
#define SMB_WN  81920                  // 16384
#define SMB_AG  98304                  // [32][64] f32 = 8192
#define SMB_PRM 106496                 // 5*64+8 f32
#define SMB_TOT (106496 + 1312)

// =====================================================================
// Kernel 1b2: softmax + agg + linear + BN + SELU + scores.
// grid (8, 16), block 256 (8 warps). Warp owns 4 i's; barrier-free
// after staging (warp-synchronous shuffles + own smem regions only).
// =====================================================================
__global__ __launch_bounds__(256, 2)
void k1b2_fused(const float* __restrict__ x,
                const float* __restrict__ Wpwa, const float* __restrict__ bpwa,
                const float* __restrict__ Wpna, const float* __restrict__ bpna,
                const float* __restrict__ bnsc, const float* __restrict__ bnbi,
                const float* __restrict__ poolw, const float* __restrict__ poolb)
{
    extern __shared__ char sm2[];
    float* xs   = (float*)(sm2 + SMB_XS);
    float* Wa   = (float*)(sm2 + SMB_WA);
    float* Wn   = (float*)(sm2 + SMB_WN);
    float* aggs = (float*)(sm2 + SMB_AG);
    float* prm  = (float*)(sm2 + SMB_PRM);

    const int tid = threadIdx.x;
    const int lane = tid & 31, w = tid >> 5;
    const int b  = blockIdx.y;
    const int i0 = blockIdx.x * 32;
    const float* xb = x + (size_t)b * NN * DD;

    // stage x_b (64KB), W's (natural [d][e] layout), params
    for (int t = tid; t < 4096; t += 256)
        ((float4*)xs)[t] = ((const float4*)xb)[t];
    for (int t = tid; t < 1024; t += 256) {
        ((float4*)Wa)[t] = ((const float4*)Wpwa)[t];
        ((float4*)Wn)[t] = ((const float4*)Wpna)[t];
    }
    if (tid < 64) {
        prm[tid]       = bpwa[tid] + bpna[tid];
        prm[64 + tid]  = bnsc[tid] * rsqrtf(1.0f + 1e-5f);
        prm[128 + tid] = bnbi[tid];
        prm[192 + tid] = poolw[tid];
    }
    if (tid == 0) prm[320] = poolb[0];
    __syncthreads();

    const int d0 = lane * 2;
    const int e0 = lane * 2;

    for (int c = 0; c < 4; ++c) {
        const int iL = w * 4 + c;          // local 0..31
        const int ig = i0 + iL;            // global node

        // ---- softmax over 256 j (warp-only) ----
        const float* lrow = g_logits + ((size_t)b * NN + ig) * NN;
        float4 va = ((const float4*)lrow)[lane];
        float4 vb = ((const float4*)lrow)[32 + lane];
        float av[8] = { va.x, va.y, va.z, va.w, vb.x, vb.y, vb.z, vb.w };

        float m = av[0];
        #pragma unroll
        for (int k = 1; k < 8; ++k) m = fmaxf(m, av[k]);
        #pragma unroll
        for (int o = 16; o; o >>= 1) m = fmaxf(m, __shfl_xor_sync(0xffffffffu, m, o));

        float s = 0.f;
        #pragma unroll
        for (int k = 0; k < 8; ++k) { av[k] = ex2f((av[k] - m) * LOG2E); s += av[k]; }
        #pragma unroll
        for (int o = 16; o; o >>= 1) s += __shfl_xor_sync(0xffffffffu, s, o);
        float inv = 1.f / s;
        #pragma unroll
        for (int k = 0; k < 8; ++k) av[k] *= inv;

        // ---- agg[d0,d0+1] = sum_j A[j] * x[j][d] (smem, shuffle bcast) ----
        float ax0 = 0.f, ay0 = 0.f, ax1 = 0.f, ay1 = 0.f;
        #pragma unroll 4
        for (int src = 0; src < 32; ++src) {
            #pragma unroll
            for (int k = 0; k < 8; ++k) {
                float A = __shfl_sync(0xffffffffu, av[k], src);
                int j = src * 4 + (k & 3) + ((k & 4) << 5);
                float2 xv = *(const float2*)(xs + j * 64 + d0);
                if (k < 4) { ax0 = fmaf(A, xv.x, ax0); ay0 = fmaf(A, xv.y, ay0); }
                else       { ax1 = fmaf(A, xv.x, ax1); ay1 = fmaf(A, xv.y, ay1); }
            }
        }
        *(float2*)(aggs + iL * 64 + d0) = make_float2(ax0 + ax1, ay0 + ay1);
        __syncwarp();

        // ---- linear + BN + SELU + score (warp-only) ----
        float ha0 = 0.f, ha1 = 0.f, hn0 = 0.f, hn1 = 0.f;
        #pragma unroll 8
        for (int d = 0; d < 64; ++d) {
            float ad = aggs[iL * 64 + d];
            float xd = xs[ig * 64 + d];
            float2 wa = *(const float2*)(Wa + d * 64 + e0);
            float2 wn = *(const float2*)(Wn + d * 64 + e0);
            ha0 = fmaf(ad, wa.x, ha0); ha1 = fmaf(ad, wa.y, ha1);
            hn0 = fmaf(xd, wn.x, hn0); hn1 = fmaf(xd, wn.y, hn1);
        }
        float h0 = ha0 + hn0 + prm[e0];
        float h1 = ha1 + hn1 + prm[e0 + 1];
        h0 = h0 * prm[64 + e0] + prm[128 + e0];
        h1 = h1 * prm[64 + e0 + 1] + prm[128 + e0 + 1];
        h0 = 1.0507009873554805f *
             (h0 > 0.f ? h0 : 1.6732632423543772f * (__expf(h0) - 1.f));
        h1 = 1.0507009873554805f *
             (h1 > 0.f ? h1 : 1.6732632423543772f * (__expf(h1) - 1.f));
        *(float2*)(g_h + ((size_t)b * NN + ig) * DD + e0) = make_float2(h0, h1);

        float r = h0 * prm[192 + e0] + h1 * prm[192 + e0 + 1];
        #pragma unroll
        for (int o = 16; o; o >>= 1) r += __shfl_xor_sync(0xffffffffu, r, o);
        if (lane == 0)
            g_scores[b * NN + ig] = 1.f / (1.f + __expf(-(r + prm[320])));
    }
}

// =====================================================================
// Kernel 3: stable top-k + gather. grid (8 slices, 16 b), block 256.
// =====================================================================
__global__ __launch_bounds__(256)
void k3_topk(float* __restrict__ out)
{
    __shared__ float sc[NN];
    __shared__ int src[KTOP];
    const int tid = threadIdx.x;
    const int b = blockIdx.y;
    const int s0 = blockIdx.x * 16;

    float s = g_scores[b * NN + tid];
    sc[tid] = s;
    __syncthreads();

    int rank = 0;
    #pragma unroll 8
    for (int j = 0; j < NN; ++j) {
        float sj = sc[j];
        rank += (sj > s) || (sj == s && j < tid);
    }
    if (rank < KTOP) src[rank] = tid;
    __syncthreads();

    {
        int r = s0 + (tid >> 4), q = tid & 15;
        int j = src[r];
        float w = sc[j];
        float4 v = ((const float4*)(g_h + ((size_t)b * NN + j) * DD))[q];
        v.x *= w; v.y *= w; v.z *= w; v.w *= w;
        ((float4*)(out + ((size_t)b * KTOP + r) * DD))[q] = v;
    }
}

// =====================================================================
extern "C" void kernel_launch(void* const* d_in, const int* in_sizes, int n_in,
                              void* d_out, int out_size)
{
    const float* x     = (const float*)d_in[0];
    const float* Watt  = (const float*)d_in[1];
    const float* batt  = (const float*)d_in[2];
    const float* attw  = (const float*)d_in[3];
    const float* Wpwa  = (const float*)d_in[4];
    const float* bpwa  = (const float*)d_in[5];
    const float* Wpna  = (const float*)d_in[6];
    const float* bpna  = (const float*)d_in[7];
    const float* bnsc  = (const float*)d_in[8];
    const float* bnbi  = (const float*)d_in[9];
    const float* poolw = (const float*)d_in[10];
    const float* poolb = (const float*)d_in[11];

    cudaFuncSetAttribute(k1a_logits,
                         cudaFuncAttributeMaxDynamicSharedMemorySize, SM_TOT1);
    cudaFuncSetAttribute(k1b2_fused,
                         cudaFuncAttributeMaxDynamicSharedMemorySize, SMB_TOT);

    dim3 ga(NPAIR, BB);
    k1a_logits<<<ga, 256, SM_TOT1>>>(x, Watt, batt, attw);
    dim3 gb(8, BB);
    k1b2_fused<<<gb, 256, SMB_TOT>>>(x, Wpwa, bpwa, Wpna, bpna,
                                     bnsc, bnbi, poolw, poolb);
    dim3 gc(8, BB);
    k3_topk<<<gc, 256>>>((float*)d_out);
}